// round 9
// baseline (speedup 1.0000x reference)
#include <cuda_runtime.h>

#define NTAGS 64
#define SOS_IDX 1
#define EOS_IDX 2
#define REF_TAG 3

static __device__ __forceinline__ unsigned long long pk2(float x, float y) {
    unsigned long long r;
    asm("mov.b64 %0, {%1, %2};" : "=l"(r) : "f"(x), "f"(y));
    return r;
}
static __device__ __forceinline__ void upk2(unsigned long long a, float &x, float &y) {
    asm("mov.b64 {%0, %1}, %2;" : "=f"(x), "=f"(y) : "l"(a));
}
static __device__ __forceinline__ unsigned long long fma2(unsigned long long a,
                                                          unsigned long long b,
                                                          unsigned long long c) {
    unsigned long long d;
    asm("fma.rn.f32x2 %0, %1, %2, %3;" : "=l"(d) : "l"(a), "l"(b), "l"(c));
    return d;
}
static __device__ __forceinline__ unsigned long long add2(unsigned long long a,
                                                          unsigned long long b) {
    unsigned long long d;
    asm("add.rn.f32x2 %0, %1, %2;" : "=l"(d) : "l"(a), "l"(b));
    return d;
}

__global__ void __launch_bounds__(256) crf_fwd_kernel(
    const float* __restrict__ h, const float* __restrict__ mask,
    const float* __restrict__ trans, float* __restrict__ out, int T, int B)
{
    const int tid = threadIdx.x;
    const int chain = tid >> 7;         // 0: threads 0-127, 1: threads 128-255
    const int ctid = tid & 127;         // index within the chain group
    const int w = ctid >> 5;            // warp within chain (0..3)
    const int l = ctid & 31;
    // two lanes per tag: lane l and lane l^16 split the j-range
    const int tag  = w * 16 + (l & 15);
    const int half = l >> 4;            // 0: j in [0,32), 1: j in [32,64)

    const int b = blockIdx.x + chain * gridDim.x;
    const bool active = (b < B);
    const int bsafe = active ? b : 0;

    __shared__ __align__(16) float sh_u[2][2][NTAGS];   // [chain][buf][tag]
    __shared__ float sh_red[2][4];                      // [chain][warp]

    // ---- len = sum(mask[b,:]) (mask is a prefix of ones) ----
    const float* mb = mask + (size_t)bsafe * T;
    {
        float msum = 0.0f;
        const float4* m4 = reinterpret_cast<const float4*>(mb);
        const int n4 = T >> 2;
        for (int k = ctid; k < n4; k += 128) {
            float4 v = m4[k];
            msum += (v.x + v.y) + (v.z + v.w);
        }
        #pragma unroll
        for (int o = 16; o > 0; o >>= 1) msum += __shfl_xor_sync(0xffffffffu, msum, o);
        if (l == 0) sh_red[chain][w] = msum;
    }

    // E2[k] = exp(trans[tag][half*32 + 2k..2k+1]) for this thread's j-half.
    // exp(-10000) underflows to exactly 0 -> masked transitions vanish.
    unsigned long long E2[16];
    {
        const float4* tr = reinterpret_cast<const float4*>(trans + tag * NTAGS + half * 32);
        #pragma unroll
        for (int k = 0; k < 8; k++) {
            float4 t4 = tr[k];
            E2[2 * k]     = pk2(__expf(t4.x), __expf(t4.y));
            E2[2 * k + 1] = pk2(__expf(t4.z), __expf(t4.w));
        }
    }
    const float eeos = __expf(trans[EOS_IDX * NTAGS + tag]);

    const float* hb = h + (size_t)bsafe * T * NTAGS + tag;

    __syncthreads();
    int len = active ? (int)((sh_red[chain][0] + sh_red[chain][1]) +
                             (sh_red[chain][2] + sh_red[chain][3]) + 0.5f) : 0;
    // lenmax across both chains: max of the two (uniform across CTA)
    __shared__ int sh_len[2];
    if (ctid == 0) sh_len[chain] = len;

    // raw prefetch buffers (depth 4)
    float rawh[4];
    #pragma unroll
    for (int k = 0; k < 4; k++) {
        int tp = (k < T) ? k : (T - 1);
        rawh[k] = hb[(size_t)tp * NTAGS];
    }

    // U(-1): 1 at SOS, 0 elsewhere.
    if (ctid < NTAGS) sh_u[chain][0][ctid] = (ctid == SOS_IDX) ? 1.0f : 0.0f;
    float myu = (tag == SOS_IDX) ? 1.0f : 0.0f;
    int Esum = 0;
    float ehcur = __expf(rawh[0]);      // exp computed one full step ahead
    __syncthreads();
    const int lenmax = (sh_len[0] > sh_len[1]) ? sh_len[0] : sh_len[1];

    #pragma unroll 4
    for (int t = 0; t < lenmax; t++) {
        if (t < len) {                  // chain-uniform guard
            // prefetch h for t+4 (clamped) and exp for t+1: fully hidden
            int tp = t + 4;
            tp = (tp < T) ? tp : (T - 1);
            float fresh = hb[(size_t)tp * NTAGS];
            float ehnext = __expf(rawh[(t + 1) & 3]);   // loaded at t-3
            rawh[t & 3] = fresh;
            const float eh = ehcur;
            ehcur = ehnext;

            const float* up = sh_u[chain][t & 1];
            float* un = sh_u[chain][(t + 1) & 1];

            // half-dot: 8 front-batched LDS.128 + 16 fma2, 4 accumulators
            const float4* pv = reinterpret_cast<const float4*>(up) + half * 8;
            float4 pa[8];
            #pragma unroll
            for (int k = 0; k < 8; k++) pa[k] = pv[k];

            // exact power-of-two renormalizer (ALU-only, off the dot path)
            const unsigned int ub = __float_as_uint(up[REF_TAG]);
            int e = (int)((ub >> 23) & 0xffu) - 127;
            e = (ub == 0u) ? 0 : e;     // t==0: uref is exactly 0
            const float scale = __uint_as_float((unsigned)(127 - e) << 23);
            Esum += e;
            const float es = eh * scale;

            unsigned long long acc[4];
            #pragma unroll
            for (int k = 0; k < 8; k++) {
                const int a0 = (k & 1) * 2;
                unsigned long long lo = fma2(E2[2 * k],     pk2(pa[k].x, pa[k].y),
                                             (k < 2) ? 0ull : acc[a0]);
                unsigned long long hi = fma2(E2[2 * k + 1], pk2(pa[k].z, pa[k].w),
                                             (k < 2) ? 0ull : acc[a0 + 1]);
                acc[a0] = lo; acc[a0 + 1] = hi;
            }
            unsigned long long sA = add2(add2(acc[0], acc[2]), add2(acc[1], acc[3]));
            float vx, vy;
            upk2(sA, vx, vy);
            const float vhalf = vx + vy;

            // combine the two j-halves (partner lane l^16, same warp)
            const float vfull = vhalf + __shfl_xor_sync(0xffffffffu, vhalf, 16);

            const float u = es * vfull;     // identical in both partner lanes
            un[tag] = u;                    // both lanes store the same value
            myu = u;
        }
        __syncthreads();                    // one cheap barrier, both chains
    }

    // out[b] = Esum*ln2 + log( sum_i U_i * exp(trans[EOS,i]) )
    float term = (half == 0) ? myu * eeos : 0.0f;
    #pragma unroll
    for (int o = 16; o > 0; o >>= 1) term += __shfl_xor_sync(0xffffffffu, term, o);
    __syncthreads();                        // sh_red reuse safety
    if (l == 0) sh_red[chain][w] = term;
    __syncthreads();
    if (ctid == 0 && active) {
        out[b] = (float)Esum * 0.6931471805599453f +
                 __logf((sh_red[chain][0] + sh_red[chain][1]) +
                        (sh_red[chain][2] + sh_red[chain][3]));
    }
}

extern "C" void kernel_launch(void* const* d_in, const int* in_sizes, int n_in,
                              void* d_out, int out_size) {
    const float* h     = (const float*)d_in[0];   // [B, T, 64]
    const float* mask  = (const float*)d_in[1];   // [B, T]
    const float* trans = (const float*)d_in[2];   // [64, 64]
    float* out = (float*)d_out;                   // [B]
    const int B = out_size;
    const int T = in_sizes[1] / B;
    const int grid = (B + 1) / 2;
    crf_fwd_kernel<<<grid, 256>>>(h, mask, trans, out, T, B);
}

// round 10
// speedup vs baseline: 1.7948x; 1.7948x over previous
#include <cuda_runtime.h>

#define NTAGS 64
#define SOS_IDX 1
#define EOS_IDX 2
#define REF_TAG 3

static __device__ __forceinline__ unsigned long long pk2(float x, float y) {
    unsigned long long r;
    asm("mov.b64 %0, {%1, %2};" : "=l"(r) : "f"(x), "f"(y));
    return r;
}
static __device__ __forceinline__ void upk2(unsigned long long a, float &x, float &y) {
    asm("mov.b64 {%0, %1}, %2;" : "=f"(x), "=f"(y) : "l"(a));
}
static __device__ __forceinline__ unsigned long long fma2(unsigned long long a,
                                                          unsigned long long b,
                                                          unsigned long long c) {
    unsigned long long d;
    asm("fma.rn.f32x2 %0, %1, %2, %3;" : "=l"(d) : "l"(a), "l"(b), "l"(c));
    return d;
}
static __device__ __forceinline__ unsigned long long add2(unsigned long long a,
                                                          unsigned long long b) {
    unsigned long long d;
    asm("add.rn.f32x2 %0, %1, %2;" : "=l"(d) : "l"(a), "l"(b));
    return d;
}

__global__ void __launch_bounds__(NTAGS) crf_fwd_kernel(
    const float* __restrict__ h, const float* __restrict__ mask,
    const float* __restrict__ trans, float* __restrict__ out, int T)
{
    const int b = blockIdx.x;
    const int i = threadIdx.x;          // one thread per tag
    const int warp = i >> 5;
    const int lane = i & 31;

    __shared__ __align__(16) float sh_u[2][NTAGS];
    __shared__ float sh_red[2];

    // ---- len = sum(mask[b,:]) once (mask is a prefix of ones) ----
    const float* mb = mask + (size_t)b * T;
    float msum = 0.0f;
    {
        const float4* m4 = reinterpret_cast<const float4*>(mb);
        const int n4 = T >> 2;
        for (int k = i; k < n4; k += NTAGS) {
            float4 v = m4[k];
            msum += (v.x + v.y) + (v.z + v.w);
        }
        #pragma unroll
        for (int o = 16; o > 0; o >>= 1) msum += __shfl_xor_sync(0xffffffffu, msum, o);
        if (lane == 0) sh_red[warp] = msum;
    }

    // E[i][j] = exp(trans[i][j]) packed as f32x2 (constant over t).
    // exp(-10000) underflows to exactly 0 -> masked transitions vanish.
    unsigned long long E2[NTAGS / 2];
    {
        const float4* tr = reinterpret_cast<const float4*>(trans + i * NTAGS);
        #pragma unroll
        for (int k = 0; k < NTAGS / 4; k++) {
            float4 t4 = tr[k];
            E2[2 * k]     = pk2(__expf(t4.x), __expf(t4.y));
            E2[2 * k + 1] = pk2(__expf(t4.z), __expf(t4.w));
        }
    }
    const float eeos = __expf(trans[EOS_IDX * NTAGS + i]);

    const float* hb = h + (size_t)b * T * NTAGS + i;

    __syncthreads();
    const int len = (int)(sh_red[0] + sh_red[1] + 0.5f);   // 1 <= len <= T

    // raw prefetch buffers (depth 4)
    float rawh[4];
    #pragma unroll
    for (int k = 0; k < 4; k++) {
        int tp = (k < T) ? k : (T - 1);
        rawh[k] = hb[(size_t)tp * NTAGS];
    }

    // U(-1): 1 at SOS, 0 elsewhere.
    sh_u[0][i] = (i == SOS_IDX) ? 1.0f : 0.0f;
    float myu = (i == SOS_IDX) ? 1.0f : 0.0f;
    int Esum = 0;
    float ehcur = __expf(rawh[0]);      // exp computed one full step ahead
    __syncthreads();

    #pragma unroll 4
    for (int t = 0; t < len; t++) {
        const float* up = sh_u[t & 1];
        float* un = sh_u[(t + 1) & 1];
        const float4* pv = reinterpret_cast<const float4*>(up);

        // --- issue ALL shared loads first: renormalizer scalar + 16 LDS.128 ---
        const unsigned int ub = __float_as_uint(up[REF_TAG]);
        float4 pa[16];
        #pragma unroll
        for (int k = 0; k < 16; k++) pa[k] = pv[k];

        // independent work overlapping LDS latency: prefetch h(t+4), exp(t+1)
        int tp = t + 4;
        tp = (tp < T) ? tp : (T - 1);   // clamped, always in-bounds
        float fresh = hb[(size_t)tp * NTAGS];
        float ehnext = __expf(rawh[(t + 1) & 3]);   // operand loaded at t-3
        rawh[t & 3] = fresh;
        const float eh = ehcur;
        ehcur = ehnext;

        // exact power-of-two renormalizer (ALU-only, off the dot path)
        int e = (int)((ub >> 23) & 0xffu) - 127;
        e = (ub == 0u) ? 0 : e;             // t==0: uref is exactly 0
        const float scale = __uint_as_float((unsigned)(127 - e) << 23);
        Esum += e;
        const float es = eh * scale;

        // w_i = dot(E_row_i, U_prev): 32 fma2 into 8 independent accumulators
        unsigned long long acc[8];
        #pragma unroll
        for (int k = 0; k < 16; k++) {
            const int a0 = (k & 3) * 2;
            unsigned long long lo = fma2(E2[2 * k],     pk2(pa[k].x, pa[k].y),
                                         (k < 4) ? 0ull : acc[a0]);
            unsigned long long hi = fma2(E2[2 * k + 1], pk2(pa[k].z, pa[k].w),
                                         (k < 4) ? 0ull : acc[a0 + 1]);
            acc[a0] = lo; acc[a0 + 1] = hi;
        }
        unsigned long long sA = add2(add2(add2(acc[0], acc[2]), add2(acc[4], acc[6])),
                                     add2(add2(acc[1], acc[3]), add2(acc[5], acc[7])));
        float vx, vy;
        upk2(sA, vx, vy);
        const float w = vx + vy;

        const float u = es * w;             // U_i(t)
        un[i] = u;
        myu = u;
        __syncthreads();                    // single barrier per step
    }

    // out[b] = Esum*ln2 + log( sum_i U_i * exp(trans[EOS,i]) )
    float term = myu * eeos;
    #pragma unroll
    for (int o = 16; o > 0; o >>= 1) term += __shfl_xor_sync(0xffffffffu, term, o);
    __syncthreads();                        // sh_red reuse safety
    if (lane == 0) sh_red[warp] = term;
    __syncthreads();
    if (i == 0) {
        out[b] = (float)Esum * 0.6931471805599453f + __logf(sh_red[0] + sh_red[1]);
    }
}

extern "C" void kernel_launch(void* const* d_in, const int* in_sizes, int n_in,
                              void* d_out, int out_size) {
    const float* h     = (const float*)d_in[0];   // [B, T, 64]
    const float* mask  = (const float*)d_in[1];   // [B, T]
    const float* trans = (const float*)d_in[2];   // [64, 64]
    float* out = (float*)d_out;                   // [B]
    const int B = out_size;
    const int T = in_sizes[1] / B;
    crf_fwd_kernel<<<B, NTAGS>>>(h, mask, trans, out, T);
}